// round 15
// baseline (speedup 1.0000x reference)
#include <cuda_runtime.h>
#include <cuda_bf16.h>
#include <cstddef>

// Problem constants
#define BB    16
#define SS    4096
#define DD    1024      // D_IN
#define HH    1024
#define DOUT  1024
#define SPLIT 64
#define ROWS  (SS / SPLIT)   // 64 rows per pass1 block

// Epilogue tiling (R13-proven one-wave gemv shape)
#define KS    4                    // K-splits
#define CF4   ((DD / KS) / 4)      // 64 float4 per chunk
#define NPW   2                    // n-rows per warp
#define NPB   (16 * NPW)           // 32 n-rows per block (16 warps)
#define NBLK  128                  // 1 block/SM, co-resident (<=148)

// Scratch: __device__ globals (no cudaMalloc allowed)
__device__ float g_partial[BB * SPLIT * DD];   // pass1 partials, 4 MB
__device__ float g_m[BB * DD];                 // mean, 64 KB
__device__ float g_pA[KS * BB * HH];           // gemvA partials, 256 KB
__device__ float g_pB[KS * BB * DOUT];         // gemvB partials, 256 KB

// Grid-barrier state (self-resetting counter: graph-replay-safe)
__device__ unsigned g_ctr = 0;
__device__ unsigned g_gen = 0;

__device__ __forceinline__ void grid_bar() {
    __syncthreads();
    if (threadIdx.x == 0) {
        __threadfence();
        volatile unsigned* vgen = &g_gen;
        const unsigned gen = *vgen;                    // read BEFORE arriving
        const unsigned prev = atomicAdd(&g_ctr, 1u);
        if (prev == NBLK - 1u) {
            g_ctr = 0u;
            __threadfence();
            atomicAdd(&g_gen, 1u);                     // release
        } else {
            while (*vgen == gen) { }
        }
        __threadfence();
    }
    __syncthreads();
}

// ---------------------------------------------------------------------------
// Pass 1: partial sums over S. grid = (SPLIT, B) = (64,16), block = 256.
// (Proven 41 us streaming config — untouched.)
// ---------------------------------------------------------------------------
__global__ __launch_bounds__(256) void pass1_kernel(const float* __restrict__ x) {
    const int split = blockIdx.x;
    const int b     = blockIdx.y;
    const int t     = threadIdx.x;

    const float4* xp = reinterpret_cast<const float4*>(
        x + ((size_t)b * SS + (size_t)split * ROWS) * DD);

    float4 acc = make_float4(0.f, 0.f, 0.f, 0.f);
    #pragma unroll 16
    for (int r = 0; r < ROWS; ++r) {
        float4 v = __ldcs(&xp[(size_t)r * (DD / 4) + t]);
        acc.x += v.x; acc.y += v.y; acc.z += v.z; acc.w += v.w;
    }

    float4* out = reinterpret_cast<float4*>(
        g_partial + ((size_t)b * SPLIT + split) * DD);
    out[t] = acc;
}

// ---------------------------------------------------------------------------
// Butterfly: 31 shuffles; lane L exits holding output with orig index L
// (n_local = L>>4, b = L&15).
// ---------------------------------------------------------------------------
__device__ __forceinline__ float butterfly32(float acc[32], int lane) {
    #pragma unroll
    for (int step = 0; step < 5; ++step) {
        const int off = 16 >> step;
        const int m   = 32 >> step;
        const bool hi = (lane & off) != 0;
        #pragma unroll
        for (int i = 0; i < 32; ++i) {
            if (i < m / 2) {
                float tmp  = hi ? acc[i] : acc[i + m / 2];
                float recv = __shfl_xor_sync(0xffffffffu, tmp, off);
                acc[i] = (hi ? acc[i + m / 2] : acc[i]) + recv;
            }
        }
    }
    return acc[0];
}

// ---------------------------------------------------------------------------
// Fused epilogue: mean -> gemvA -> gemvB -> out. ONE launch, 3 grid barriers.
// grid = 128 blocks x 512 threads (16 warps/SM, 1 blk/SM, one wave).
// Block mapping for both gemv phases: ks = blk&3, ng = blk>>2 (0..31),
// warp w owns n-rows {ng*32 + 2w, +1}. Inner loop identical to R13's proven
// 6.5us gemv. W_out is register-preloaded during phase A (R12-validated).
// ---------------------------------------------------------------------------
__global__ __launch_bounds__(512, 1) void fused_epilogue_kernel(
    const float* __restrict__ W_enc,
    const float* __restrict__ b_enc,
    const float* __restrict__ W_out,
    const float* __restrict__ b_out,
    float* __restrict__ out)
{
    __shared__ float4 sV[BB * CF4];   // 16 KB
    __shared__ float  sred[512];

    const int t    = threadIdx.x;
    const int blk  = blockIdx.x;
    const int warp = t >> 5;
    const int lane = t & 31;
    const int ks   = blk & 3;
    const int ng   = blk >> 2;
    const int n    = ng * NPB + warp * NPW;

    // ---- P1: mean. 128 outputs/block, 4 threads per output ----------------
    {
        const int q = t >> 7;                    // quarter 0..3 (16 splits each)
        const int o = blk * 128 + (t & 127);     // 0..16383
        const int b = o >> 10;
        const int d = o & 1023;
        const float* p = g_partial + (size_t)b * SPLIT * DD
                       + (size_t)q * 16 * DD + d;
        float s = 0.f;
        #pragma unroll
        for (int i = 0; i < 16; ++i) s += p[(size_t)i * DD];
        sred[t] = s;
        __syncthreads();
        if (q == 0) {
            g_m[o] = (sred[t] + sred[t + 128] + sred[t + 256] + sred[t + 384])
                     * (1.0f / (float)SS);
        }
    }
    grid_bar();

    // ---- P2: gemvA = m @ W_enc^T  (R13 shape) -----------------------------
    {
        const float4* V4 = reinterpret_cast<const float4*>(g_m);
        #pragma unroll
        for (int i = 0; i < 2; ++i) {
            const int id = i * 512 + t;          // 0..1023
            const int b  = id >> 6;
            const int k4 = id & 63;
            sV[id] = V4[(size_t)b * (DD / 4) + (size_t)ks * CF4 + k4];
        }
    }
    __syncthreads();

    const size_t wbase = (size_t)ks * CF4 + lane;
    const float4* WE = reinterpret_cast<const float4*>(W_enc);
    float4 w0a = WE[(size_t)(n    ) * (DD / 4) + wbase];
    float4 w0b = WE[(size_t)(n    ) * (DD / 4) + wbase + 32];
    float4 w1a = WE[(size_t)(n + 1) * (DD / 4) + wbase];
    float4 w1b = WE[(size_t)(n + 1) * (DD / 4) + wbase + 32];

    // Early W_out preload: DRAM latency hidden behind phase A + barrier
    const float4* WO = reinterpret_cast<const float4*>(W_out);
    float4 o0a = WO[(size_t)(n    ) * (DD / 4) + wbase];
    float4 o0b = WO[(size_t)(n    ) * (DD / 4) + wbase + 32];
    float4 o1a = WO[(size_t)(n + 1) * (DD / 4) + wbase];
    float4 o1b = WO[(size_t)(n + 1) * (DD / 4) + wbase + 32];

    {
        float acc[32];
        #pragma unroll
        for (int i = 0; i < 32; ++i) acc[i] = 0.f;

        #pragma unroll
        for (int b = 0; b < BB; ++b) {
            float4 ma = sV[b * CF4 + lane];
            float4 mb = sV[b * CF4 + lane + 32];
            acc[b]      += ma.x * w0a.x + ma.y * w0a.y + ma.z * w0a.z + ma.w * w0a.w
                         + mb.x * w0b.x + mb.y * w0b.y + mb.z * w0b.z + mb.w * w0b.w;
            acc[16 + b] += ma.x * w1a.x + ma.y * w1a.y + ma.z * w1a.z + ma.w * w1a.w
                         + mb.x * w1b.x + mb.y * w1b.y + mb.z * w1b.z + mb.w * w1b.w;
        }

        const float r = butterfly32(acc, lane);
        const int b_o = lane & 15;
        const int n_o = n + (lane >> 4);
        g_pA[(size_t)ks * (BB * HH) + (size_t)b_o * HH + n_o] = r;
    }
    grid_bar();

    // ---- P3: gemvB = (sum pA + b_enc) @ W_out^T  (fused fill, R13 mode 1) -
    {
        const float4* V4 = reinterpret_cast<const float4*>(g_pA);
        const float4* B4 = reinterpret_cast<const float4*>(b_enc);
        #pragma unroll
        for (int i = 0; i < 2; ++i) {
            const int id = i * 512 + t;          // 0..1023
            const int b  = id >> 6;
            const int k4 = id & 63;
            const size_t g = (size_t)b * (DD / 4) + (size_t)ks * CF4 + k4;
            float4 a0 = V4[g];
            float4 a1 = V4[g + 4096];            // slice stride BB*HH/4
            float4 a2 = V4[g + 2 * 4096];
            float4 a3 = V4[g + 3 * 4096];
            float4 bb = B4[ks * CF4 + k4];
            float4 v;
            v.x = a0.x + a1.x + a2.x + a3.x + bb.x;
            v.y = a0.y + a1.y + a2.y + a3.y + bb.y;
            v.z = a0.z + a1.z + a2.z + a3.z + bb.z;
            v.w = a0.w + a1.w + a2.w + a3.w + bb.w;
            sV[id] = v;
        }
    }
    __syncthreads();

    {
        float acc[32];
        #pragma unroll
        for (int i = 0; i < 32; ++i) acc[i] = 0.f;

        #pragma unroll
        for (int b = 0; b < BB; ++b) {
            float4 ma = sV[b * CF4 + lane];
            float4 mb = sV[b * CF4 + lane + 32];
            acc[b]      += ma.x * o0a.x + ma.y * o0a.y + ma.z * o0a.z + ma.w * o0a.w
                         + mb.x * o0b.x + mb.y * o0b.y + mb.z * o0b.z + mb.w * o0b.w;
            acc[16 + b] += ma.x * o1a.x + ma.y * o1a.y + ma.z * o1a.z + ma.w * o1a.w
                         + mb.x * o1b.x + mb.y * o1b.y + mb.z * o1b.z + mb.w * o1b.w;
        }

        const float r = butterfly32(acc, lane);
        const int b_o = lane & 15;
        const int n_o = n + (lane >> 4);
        g_pB[(size_t)ks * (BB * DOUT) + (size_t)b_o * DOUT + n_o] = r;
    }
    grid_bar();

    // ---- P4: out = sum(pB slices) + b_out. 128 outputs/block, t < 128 -----
    if (t < 128) {
        const int idx = blk * 128 + t;           // 0..16383
        float s = b_out[idx & (DOUT - 1)];
        #pragma unroll
        for (int j = 0; j < KS; ++j) s += g_pB[(size_t)j * (BB * DOUT) + idx];
        out[idx] = s;
    }
}

// ---------------------------------------------------------------------------
// Launch. Inputs (metadata order): x, W_enc, b_enc, W_out, b_out.
// 2 launches total.
// ---------------------------------------------------------------------------
extern "C" void kernel_launch(void* const* d_in, const int* in_sizes, int n_in,
                              void* d_out, int out_size)
{
    const float* x     = (const float*)d_in[0];
    const float* W_enc = (const float*)d_in[1];
    const float* b_enc = (const float*)d_in[2];
    const float* W_out = (const float*)d_in[3];
    const float* b_out = (const float*)d_in[4];
    float*       out   = (float*)d_out;

    // 1) partial sums over S
    pass1_kernel<<<dim3(SPLIT, BB), 256>>>(x);
    // 2) fused epilogue: mean + both layers + finalize (one wave, 16 warps/SM)
    fused_epilogue_kernel<<<NBLK, 512>>>(W_enc, b_enc, W_out, b_out, out);
}